// round 15
// baseline (speedup 1.0000x reference)
#include <cuda_runtime.h>
#include <cstdint>
#include <math.h>

#define BB 32
#define NN 1000
#define CC 1601
#define MM (BB*NN)          // 32000
#define TAKE_K 64
#define CAP2 65536
#define SORTN 4096

// ---------------- device scratch ----------------
__device__ float g_H[(size_t)MM * 128];
__device__ float g_SO[(size_t)MM * 128];               // cols 0-63 = S, 64-127 = O
__device__ unsigned short g_K[(size_t)BB * NN * NN];   // u16 order keys
__device__ unsigned g_cnt1[BB * 2048];
__device__ unsigned g_cnt2[BB * 32];
__device__ unsigned g_ccnt[BB];
__device__ int      g_b1[BB];
__device__ unsigned g_cntgt1[BB];
__device__ unsigned long long g_cand[(size_t)BB * CAP2];  // (key16<<32)|flat

// ---------------- helpers ----------------
__device__ __forceinline__ unsigned flip_bits(unsigned x)
{
    return x ^ ((x & 0x80000000u) ? 0xFFFFFFFFu : 0x80000000u);
}

__device__ __forceinline__ unsigned long long pack_key(float s, unsigned flat)
{
    unsigned u = __float_as_uint(s);
    u = (u & 0x80000000u) ? ~u : (u | 0x80000000u);
    return (((unsigned long long)u) << 32) | (unsigned)(0xFFFFFFFFu - flat);
}

__device__ __forceinline__ float sigmoidf_dev(float v)
{
    return 1.f / (1.f + expf(-v));
}

__device__ __forceinline__ unsigned long long dup2(float x)
{
    unsigned long long r;
    unsigned u = __float_as_uint(x);
    asm("mov.b64 %0, {%1, %1};" : "=l"(r) : "r"(u));
    return r;
}

__device__ __forceinline__ unsigned long long pack2(float lo, float hi)
{
    unsigned long long r;
    asm("mov.b64 %0, {%1, %2};" : "=l"(r) : "r"(__float_as_uint(lo)), "r"(__float_as_uint(hi)));
    return r;
}

#define FFMA2(acc, a, b) asm("fma.rn.f32x2 %0, %1, %2, %0;" : "+l"(acc) : "l"(a), "l"(b))

// ---------------- GEMM1: R14 shape, B pre-duplicated in smem; fused counter zeroing ----------------
__global__ void __launch_bounds__(256) k_gemm1(
    const float* __restrict__ X,
    const float* __restrict__ Ws1, const float* __restrict__ bs1,
    const float* __restrict__ Wo1, const float* __restrict__ bo1)
{
    __shared__ float As[2][16][128];
    __shared__ __align__(16) unsigned long long Bs2u[2][16][128];

    const int tid = threadIdx.x;
    const int bx = blockIdx.x;
    const int row0 = bx * 128;
    const int tm = tid >> 4;
    const int tn = tid & 15;

    // fused zeroing of selection counters (gemm1 strictly precedes k_score/pass2)
    if (bx < 8) {
        for (int i = bx * 8192 + tid; i < (bx + 1) * 8192; i += 256) g_cnt1[i] = 0;
        if (bx == 0) {
            for (int i = tid; i < BB * 32; i += 256) g_cnt2[i] = 0;
            if (tid < BB) g_ccnt[tid] = 0;
        }
    }

    const int arow = tid >> 1;
    const int aseg = (tid & 1) * 8;
    const float* xrow = X + (size_t)(row0 + arow) * CC;

    float aR[8], bR[8];

#define G1_LOAD(K0)                                                          \
    {                                                                        \
        _Pragma("unroll")                                                    \
        for (int i = 0; i < 8; i++) aR[i] = xrow[(K0) + aseg + i];           \
        _Pragma("unroll")                                                    \
        for (int i = 0; i < 8; i++) {                                        \
            int idx = tid + i * 256;                                         \
            int k = (K0) + (idx >> 7);                                       \
            int cc = idx & 127;                                              \
            bR[i] = (cc < 64) ? Ws1[k * 64 + cc] : Wo1[k * 64 + (cc - 64)];  \
        }                                                                    \
    }

#define G1_STORE(BUF)                                                        \
    {                                                                        \
        _Pragma("unroll")                                                    \
        for (int i = 0; i < 8; i++) As[BUF][aseg + i][arow] = aR[i];         \
        _Pragma("unroll")                                                    \
        for (int i = 0; i < 8; i++) {                                        \
            int idx = tid + i * 256;                                         \
            int cc = idx & 127;                                              \
            Bs2u[BUF][idx >> 7][(cc & 7) * 16 + (cc >> 3)] = dup2(bR[i]);    \
        }                                                                    \
    }

    unsigned long long acc2[4][8];
#pragma unroll
    for (int p = 0; p < 4; p++)
#pragma unroll
        for (int j = 0; j < 8; j++) acc2[p][j] = 0ull;

    G1_LOAD(0);
    G1_STORE(0);
    __syncthreads();

    int cur = 0;
    for (int it = 0; it < 100; it++, cur ^= 1) {
        const bool hasNext = (it < 99);
        if (hasNext) G1_LOAD((it + 1) * 16);

#pragma unroll
        for (int kk = 0; kk < 16; kk++) {
            ulonglong2 a01 = *(const ulonglong2*)(&As[cur][kk][tm * 8]);
            ulonglong2 a23 = *(const ulonglong2*)(&As[cur][kk][tm * 8 + 4]);
            unsigned long long ap[4] = {a01.x, a01.y, a23.x, a23.y};
#pragma unroll
            for (int j = 0; j < 8; j++) {
                unsigned long long bd = Bs2u[cur][kk][j * 16 + tn];
                FFMA2(acc2[0][j], ap[0], bd);
                FFMA2(acc2[1][j], ap[1], bd);
                FFMA2(acc2[2][j], ap[2], bd);
                FFMA2(acc2[3][j], ap[3], bd);
            }
        }

        if (hasNext) G1_STORE(cur ^ 1);
        __syncthreads();
    }

    // ---- K tail: k = 1600 ----
    {
        const int kt = CC - 1;
        unsigned long long at[4];
#pragma unroll
        for (int p = 0; p < 4; p++) {
            int r = row0 + tm * 8 + 2 * p;
            at[p] = pack2(X[(size_t)r * CC + kt], X[(size_t)(r + 1) * CC + kt]);
        }
#pragma unroll
        for (int j = 0; j < 8; j++) {
            int col = tn * 8 + j;
            float bv = (col < 64) ? Ws1[kt * 64 + col] : Wo1[kt * 64 + (col - 64)];
            unsigned long long bd = dup2(bv);
#pragma unroll
            for (int p = 0; p < 4; p++)
                FFMA2(acc2[p][j], at[p], bd);
        }
    }

#pragma unroll
    for (int j = 0; j < 8; j++) {
        int col = tn * 8 + j;
        float bias = (col < 64) ? bs1[col] : bo1[col - 64];
#pragma unroll
        for (int p = 0; p < 4; p++) {
            float lo = __uint_as_float((unsigned)acc2[p][j]);
            float hi = __uint_as_float((unsigned)(acc2[p][j] >> 32));
            g_H[(size_t)(row0 + tm * 8 + 2 * p)     * 128 + col] = fmaxf(lo + bias, 0.f);
            g_H[(size_t)(row0 + tm * 8 + 2 * p + 1) * 128 + col] = fmaxf(hi + bias, 0.f);
        }
    }
}

// ---------------- GEMM2 (R14 verbatim): 64-row x 128-col tiles, FFMA2 ----------------
#define G2_SMEM_FLOATS (128*68 + 128*64)   // 16896
__global__ void __launch_bounds__(256) k_gemm2(
    const float* __restrict__ Ws2, const float* __restrict__ bs2,
    const float* __restrict__ Wo2, const float* __restrict__ bo2)
{
    extern __shared__ float sm2[];
    float (*Ht)[68]  = (float(*)[68])sm2;
    float (*W2s)[64] = (float(*)[64])(sm2 + 128 * 68);

    const int tid = threadIdx.x;
    const int r0 = blockIdx.x * 64;

    for (int i = tid; i < 4096; i += 256) {
        W2s[i >> 6][i & 63] = Ws2[i];
        W2s[64 + (i >> 6)][i & 63] = Wo2[i];
    }
    for (int e4 = tid; e4 < 2048; e4 += 256) {
        int r = e4 >> 5;
        int h4 = e4 & 31;
        float4 v = *(const float4*)(g_H + (size_t)(r0 + r) * 128 + h4 * 4);
        Ht[h4 * 4 + 0][r] = v.x;
        Ht[h4 * 4 + 1][r] = v.y;
        Ht[h4 * 4 + 2][r] = v.z;
        Ht[h4 * 4 + 3][r] = v.w;
    }
    __syncthreads();

    const int tm = tid >> 4;
    const int tn = tid & 15;
    const int hoff = (tn >= 8) ? 64 : 0;
    const int cbase = (tn & 7) * 8;

    unsigned long long acc2[2][8];
#pragma unroll
    for (int p = 0; p < 2; p++)
#pragma unroll
        for (int j = 0; j < 8; j++) acc2[p][j] = 0ull;

#pragma unroll 4
    for (int hh = 0; hh < 64; hh++) {
        const int h = hoff + hh;
        ulonglong2 a01 = *(const ulonglong2*)(&Ht[h][tm * 4]);
        unsigned long long ap[2] = {a01.x, a01.y};
        float4 w0 = *(const float4*)(&W2s[h][cbase]);
        float4 w1 = *(const float4*)(&W2s[h][cbase + 4]);
        unsigned long long bd[8] = {
            dup2(w0.x), dup2(w0.y), dup2(w0.z), dup2(w0.w),
            dup2(w1.x), dup2(w1.y), dup2(w1.z), dup2(w1.w)};
#pragma unroll
        for (int j = 0; j < 8; j++) {
            FFMA2(acc2[0][j], ap[0], bd[j]);
            FFMA2(acc2[1][j], ap[1], bd[j]);
        }
    }

    float b2v[8];
#pragma unroll
    for (int j = 0; j < 8; j++) {
        int col = hoff + cbase + j;
        b2v[j] = (col < 64) ? bs2[col] : bo2[col - 64];
    }
#pragma unroll
    for (int p = 0; p < 2; p++) {
        float lo[8], hi[8];
#pragma unroll
        for (int j = 0; j < 8; j++) {
            lo[j] = __uint_as_float((unsigned)acc2[p][j]) + b2v[j];
            hi[j] = __uint_as_float((unsigned)(acc2[p][j] >> 32)) + b2v[j];
        }
        float* rlo = g_SO + (size_t)(r0 + tm * 4 + 2 * p)     * 128 + hoff + cbase;
        float* rhi = g_SO + (size_t)(r0 + tm * 4 + 2 * p + 1) * 128 + hoff + cbase;
        *(float4*)rlo       = make_float4(lo[0], lo[1], lo[2], lo[3]);
        *(float4*)(rlo + 4) = make_float4(lo[4], lo[5], lo[6], lo[7]);
        *(float4*)rhi       = make_float4(hi[0], hi[1], hi[2], hi[3]);
        *(float4*)(rhi + 4) = make_float4(hi[4], hi[5], hi[6], hi[7]);
    }
}

// ============ Score GEMM: O pre-duplicated in smem; u16 keys + 2048-bin histogram ============
// smem floats: Ss [0..8448) 64x132; Os2u u64 [8448..24832); hist [24832..26880)
#define SCORE_SMEM_FLOATS 26880
__global__ void __launch_bounds__(256, 2) k_score()
{
    extern __shared__ float sm[];
    float (*Ss)[132] = (float(*)[132])sm;
    unsigned long long (*Os2u)[128] = (unsigned long long(*)[128])(sm + 8448);
    unsigned* hist = (unsigned*)(sm + 24832);

    const int tid = threadIdx.x;
    const int b  = blockIdx.z;
    const int i0 = blockIdx.y * 128;
    const int j0 = blockIdx.x * 128;

    for (int h = tid; h < 2048; h += 256) hist[h] = 0;

    for (int e = tid; e < 8192; e += 256) {
        int ii = e >> 6;
        int d  = e & 63;
        int gi = i0 + ii;
        int gj = j0 + ii;
        Ss[d][ii] = (gi < NN) ? g_SO[((size_t)(b * NN + gi)) * 128 + d] : 0.f;
        float ov = (gj < NN) ? g_SO[((size_t)(b * NN + gj)) * 128 + 64 + d] : 0.f;
        Os2u[d][(ii & 7) * 16 + (ii >> 3)] = dup2(ov);
    }
    __syncthreads();

    const int tm = tid >> 4;
    const int tn = tid & 15;

    unsigned long long acc2[4][8];
#pragma unroll
    for (int p = 0; p < 4; p++)
#pragma unroll
        for (int j = 0; j < 8; j++) acc2[p][j] = 0ull;

#pragma unroll 4
    for (int kk = 0; kk < 64; kk++) {
        ulonglong2 a01 = *(const ulonglong2*)(&Ss[kk][tm * 8]);
        ulonglong2 a23 = *(const ulonglong2*)(&Ss[kk][tm * 8 + 4]);
        unsigned long long ap[4] = {a01.x, a01.y, a23.x, a23.y};
#pragma unroll
        for (int j = 0; j < 8; j++) {
            unsigned long long bd = Os2u[kk][j * 16 + tn];
            FFMA2(acc2[0][j], ap[0], bd);
            FFMA2(acc2[1][j], ap[1], bd);
            FFMA2(acc2[2][j], ap[2], bd);
            FFMA2(acc2[3][j], ap[3], bd);
        }
    }

    const int gj0 = j0 + tn * 8;
    if (gj0 < NN) {
#pragma unroll
        for (int p = 0; p < 4; p++) {
#pragma unroll
            for (int half = 0; half < 2; half++) {
                int gi = i0 + tm * 8 + 2 * p + half;
                if (gi >= NN) continue;
                unsigned u[8];
#pragma unroll
                for (int j = 0; j < 8; j++) {
                    unsigned vb = half ? (unsigned)(acc2[p][j] >> 32)
                                       : (unsigned)acc2[p][j];
                    u[j] = flip_bits(vb);
                    atomicAdd(&hist[u[j] >> 21], 1u);
                }
                uint4 packed;
                packed.x = (u[0] >> 16) | (u[1] & 0xFFFF0000u);
                packed.y = (u[2] >> 16) | (u[3] & 0xFFFF0000u);
                packed.z = (u[4] >> 16) | (u[5] & 0xFFFF0000u);
                packed.w = (u[6] >> 16) | (u[7] & 0xFFFF0000u);
                *(uint4*)(g_K + ((size_t)b * NN + gi) * NN + gj0) = packed;
            }
        }
    }
    __syncthreads();
    for (int h = tid; h < 2048; h += 256) {
        unsigned c = hist[h];
        if (c) atomicAdd(&g_cnt1[b * 2048 + h], c);
    }
}

// ---------------- threshold over 2048 bins ----------------
__global__ void __launch_bounds__(256) k_thresh1()
{
    __shared__ unsigned seg[256];
    __shared__ unsigned scan[256];
    const int b = blockIdx.x;
    const int t = threadIdx.x;
    const unsigned* hist = g_cnt1 + b * 2048;

    unsigned s = 0;
#pragma unroll
    for (int q = 0; q < 8; q++) s += hist[2047 - (t * 8 + q)];
    seg[t] = s;
    scan[t] = s;
    __syncthreads();
    for (int off = 1; off < 256; off <<= 1) {
        unsigned v = (t >= off) ? scan[t - off] : 0u;
        __syncthreads();
        scan[t] += v;
        __syncthreads();
    }
    unsigned inc = scan[t];
    unsigned exc = inc - seg[t];
    if (exc < 64u && inc >= 64u) {
        unsigned cum = exc;
        for (int q = 0; q < 8; q++) {
            int bin = 2047 - (t * 8 + q);
            unsigned c = hist[bin];
            if (cum + c >= 64u) { g_b1[b] = bin; g_cntgt1[b] = cum; break; }
            cum += c;
        }
    }
}

// ---- pass 2 (SIMD fast path): emit key16 >= (B1<<5)-1; 32-bin sub-hist of bin1==B1 ----
__global__ void __launch_bounds__(256) k_pass2()
{
    __shared__ unsigned h2[32];
    const int b = blockIdx.y;
    const unsigned B1 = (unsigned)g_b1[b];
    unsigned lo_emit = B1 << 5;
    if (lo_emit) lo_emit--;
    if (threadIdx.x < 32) h2[threadIdx.x] = 0;
    __syncthreads();

    const uint4* K4 = (const uint4*)(g_K + (size_t)b * NN * NN);
    for (int i = blockIdx.x * 256 + threadIdx.x; i < 125000; i += 16 * 256) {
        uint4 q = K4[i];
        unsigned m4 = __vmaxu2(__vmaxu2(q.x, q.y), __vmaxu2(q.z, q.w));
        unsigned mm = m4 >> 16;
        unsigned ml = m4 & 0xFFFFu;
        if ((mm > ml ? mm : ml) < lo_emit) continue;

        unsigned w[4] = {q.x, q.y, q.z, q.w};
#pragma unroll
        for (int l = 0; l < 8; l++) {
            unsigned v = (w[l >> 1] >> ((l & 1) * 16)) & 0xFFFFu;
            if (v >= lo_emit) {
                unsigned idx = atomicAdd(&g_ccnt[b], 1u);
                if (idx < CAP2)
                    g_cand[(size_t)b * CAP2 + idx] =
                        (((unsigned long long)v) << 32) | (unsigned)(i * 8 + l);
            }
            if ((v >> 5) == B1) atomicAdd(&h2[v & 31u], 1u);
        }
    }
    __syncthreads();
    if (threadIdx.x < 32) {
        unsigned c = h2[threadIdx.x];
        if (c) atomicAdd(&g_cnt2[b * 32 + threadIdx.x], c);
    }
}

// ---- final: compute T, filter candidates, recompute exact scores, sort, output ----
__global__ void __launch_bounds__(512) k_sort(float* __restrict__ out)
{
    __shared__ unsigned long long keys[SORTN];
    __shared__ unsigned s_n;
    __shared__ unsigned s_lo;
    const int tid = threadIdx.x;
    const int b = blockIdx.x;

    if (tid == 0) {
        s_n = 0;
        unsigned K = 64u - g_cntgt1[b];
        unsigned cum = 0;
        int bsel = 0;
        for (int bin = 31; bin >= 0; bin--) {
            unsigned c = g_cnt2[b * 32 + bin];
            if (cum + c >= K) { bsel = bin; break; }
            cum += c;
        }
        unsigned T = ((unsigned)g_b1[b] << 5) | (unsigned)bsel;
        s_lo = T ? (T - 1) : 0u;
    }
    __syncthreads();
    const unsigned lo = s_lo;

    unsigned nc = g_ccnt[b];
    if (nc > CAP2) nc = CAP2;

    for (unsigned e = tid; e < nc; e += 512) {
        unsigned long long c = g_cand[(size_t)b * CAP2 + e];
        unsigned v16 = (unsigned)(c >> 32);
        if (v16 >= lo) {
            unsigned idx = atomicAdd(&s_n, 1u);
            if (idx < SORTN) {
                unsigned flat = (unsigned)c;
                int i = flat / NN;
                int j = flat % NN;
                const float4* Sr = (const float4*)(g_SO + ((size_t)(b * NN + i)) * 128);
                const float4* Or = (const float4*)(g_SO + ((size_t)(b * NN + j)) * 128 + 64);
                float acc = 0.f;
#pragma unroll
                for (int k = 0; k < 16; k++) {
                    float4 sv = Sr[k];
                    float4 ov = Or[k];
                    acc = fmaf(sv.x, ov.x, acc);
                    acc = fmaf(sv.y, ov.y, acc);
                    acc = fmaf(sv.z, ov.z, acc);
                    acc = fmaf(sv.w, ov.w, acc);
                }
                keys[idx] = pack_key(sigmoidf_dev(acc), flat);
            }
        }
    }
    __syncthreads();

    int n = (int)s_n;
    if (n > SORTN) n = SORTN;
    int m = 64;
    while (m < n) m <<= 1;
    for (int e = n + tid; e < m; e += 512) keys[e] = 0ull;

    for (int size = 2; size <= m; size <<= 1) {
        for (int stride = size >> 1; stride > 0; stride >>= 1) {
            __syncthreads();
            for (int e = tid; e < m / 2; e += 512) {
                int i = 2 * e - (e & (stride - 1));
                int j = i + stride;
                bool up = ((i & size) == 0);
                unsigned long long a = keys[i], bk = keys[j];
                bool sw = up ? (a < bk) : (a > bk);
                if (sw) { keys[i] = bk; keys[j] = a; }
            }
        }
    }
    __syncthreads();

    if (tid < 64) {
        unsigned long long key = keys[tid];
        unsigned u = (unsigned)(key >> 32);
        unsigned low = (unsigned)key;
        unsigned flat = 0xFFFFFFFFu - low;
        unsigned bits = (u & 0x80000000u) ? (u ^ 0x80000000u) : ~u;
        float s = __uint_as_float(bits);
        int subj = flat / NN;
        int obj = flat % NN;
        out[(b * TAKE_K + tid) * 2 + 0] = (float)subj;
        out[(b * TAKE_K + tid) * 2 + 1] = (float)obj;
        out[BB * TAKE_K * 2 + b * TAKE_K + tid] = s;
    }
}

// ---------------- launch ----------------
extern "C" void kernel_launch(void* const* d_in, const int* in_sizes, int n_in,
                              void* d_out, int out_size)
{
    const float* X   = (const float*)d_in[0];
    const float* Ws1 = (const float*)d_in[2];
    const float* bs1 = (const float*)d_in[3];
    const float* Ws2 = (const float*)d_in[4];
    const float* bs2 = (const float*)d_in[5];
    const float* Wo1 = (const float*)d_in[6];
    const float* bo1 = (const float*)d_in[7];
    const float* Wo2 = (const float*)d_in[8];
    const float* bo2 = (const float*)d_in[9];
    float* out = (float*)d_out;

    static int configured = 0;
    if (!configured) {
        cudaFuncSetAttribute(k_gemm2, cudaFuncAttributeMaxDynamicSharedMemorySize,
                             G2_SMEM_FLOATS * 4);
        cudaFuncSetAttribute(k_score, cudaFuncAttributeMaxDynamicSharedMemorySize,
                             SCORE_SMEM_FLOATS * 4);
        configured = 1;
    }

    k_gemm1<<<MM / 128, 256>>>(X, Ws1, bs1, Wo1, bo1);
    k_gemm2<<<MM / 64, 256, G2_SMEM_FLOATS * 4>>>(Ws2, bs2, Wo2, bo2);
    k_score<<<dim3(8, 8, BB), 256, SCORE_SMEM_FLOATS * 4>>>();
    k_thresh1<<<BB, 256>>>();
    k_pass2<<<dim3(16, BB), 256>>>();
    k_sort<<<BB, 512>>>(out);
}

// round 16
// speedup vs baseline: 1.2984x; 1.2984x over previous
#include <cuda_runtime.h>
#include <cstdint>
#include <math.h>

#define BB 32
#define NN 1000
#define CC 1601
#define MM (BB*NN)          // 32000
#define TAKE_K 64
#define CAP2 65536
#define SORTN 4096

// ---------------- device scratch ----------------
__device__ float g_H[(size_t)MM * 128];
__device__ float g_SO[(size_t)MM * 128];               // cols 0-63 = S, 64-127 = O
__device__ unsigned short g_K[(size_t)BB * NN * NN];   // u16 order keys
__device__ unsigned g_cnt1[BB * 2048];
__device__ unsigned g_cnt2[BB * 32];
__device__ unsigned g_ccnt[BB];
__device__ int      g_b1[BB];
__device__ unsigned g_cntgt1[BB];
__device__ unsigned long long g_cand[(size_t)BB * CAP2];  // (key16<<32)|flat

// ---------------- helpers ----------------
__device__ __forceinline__ unsigned flip_bits(unsigned x)
{
    return x ^ ((x & 0x80000000u) ? 0xFFFFFFFFu : 0x80000000u);
}

__device__ __forceinline__ unsigned long long pack_key(float s, unsigned flat)
{
    unsigned u = __float_as_uint(s);
    u = (u & 0x80000000u) ? ~u : (u | 0x80000000u);
    return (((unsigned long long)u) << 32) | (unsigned)(0xFFFFFFFFu - flat);
}

__device__ __forceinline__ float sigmoidf_dev(float v)
{
    return 1.f / (1.f + expf(-v));
}

__device__ __forceinline__ unsigned long long dup2(float x)
{
    unsigned long long r;
    unsigned u = __float_as_uint(x);
    asm("mov.b64 %0, {%1, %1};" : "=l"(r) : "r"(u));
    return r;
}

__device__ __forceinline__ unsigned long long pack2(float lo, float hi)
{
    unsigned long long r;
    asm("mov.b64 %0, {%1, %2};" : "=l"(r) : "r"(__float_as_uint(lo)), "r"(__float_as_uint(hi)));
    return r;
}

#define FFMA2(acc, a, b) asm("fma.rn.f32x2 %0, %1, %2, %0;" : "+l"(acc) : "l"(a), "l"(b))

// ---------------- GEMM1 (R14 verbatim + fused counter zeroing) ----------------
__global__ void __launch_bounds__(256) k_gemm1(
    const float* __restrict__ X,
    const float* __restrict__ Ws1, const float* __restrict__ bs1,
    const float* __restrict__ Wo1, const float* __restrict__ bo1)
{
    __shared__ float As[2][16][128];
    __shared__ float Bs[2][16][128];

    const int tid = threadIdx.x;
    const int bx = blockIdx.x;
    const int row0 = bx * 128;
    const int tm = tid >> 4;
    const int tn = tid & 15;

    // fused zeroing of selection counters (gemm1 strictly precedes k_score/pass2)
    if (bx < 8) {
        for (int i = bx * 8192 + tid; i < (bx + 1) * 8192; i += 256) g_cnt1[i] = 0;
        if (bx == 0) {
            for (int i = tid; i < BB * 32; i += 256) g_cnt2[i] = 0;
            if (tid < BB) g_ccnt[tid] = 0;
        }
    }

    const int arow = tid >> 1;
    const int aseg = (tid & 1) * 8;
    const float* xrow = X + (size_t)(row0 + arow) * CC;

    float aR[8], bR[8];

#define G1_LOAD(K0)                                                          \
    {                                                                        \
        _Pragma("unroll")                                                    \
        for (int i = 0; i < 8; i++) aR[i] = xrow[(K0) + aseg + i];           \
        _Pragma("unroll")                                                    \
        for (int i = 0; i < 8; i++) {                                        \
            int idx = tid + i * 256;                                         \
            int k = (K0) + (idx >> 7);                                       \
            int cc = idx & 127;                                              \
            bR[i] = (cc < 64) ? Ws1[k * 64 + cc] : Wo1[k * 64 + (cc - 64)];  \
        }                                                                    \
    }

#define G1_STORE(BUF)                                                        \
    {                                                                        \
        _Pragma("unroll")                                                    \
        for (int i = 0; i < 8; i++) As[BUF][aseg + i][arow] = aR[i];         \
        _Pragma("unroll")                                                    \
        for (int i = 0; i < 8; i++) {                                        \
            int idx = tid + i * 256;                                         \
            Bs[BUF][idx >> 7][idx & 127] = bR[i];                            \
        }                                                                    \
    }

    unsigned long long acc2[4][8];
#pragma unroll
    for (int p = 0; p < 4; p++)
#pragma unroll
        for (int j = 0; j < 8; j++) acc2[p][j] = 0ull;

    G1_LOAD(0);
    G1_STORE(0);
    __syncthreads();

    int cur = 0;
    for (int it = 0; it < 100; it++, cur ^= 1) {
        const bool hasNext = (it < 99);
        if (hasNext) G1_LOAD((it + 1) * 16);

#pragma unroll
        for (int kk = 0; kk < 16; kk++) {
            ulonglong2 a01 = *(const ulonglong2*)(&As[cur][kk][tm * 8]);
            ulonglong2 a23 = *(const ulonglong2*)(&As[cur][kk][tm * 8 + 4]);
            unsigned long long ap[4] = {a01.x, a01.y, a23.x, a23.y};
            float4 b0 = *(const float4*)(&Bs[cur][kk][tn * 8]);
            float4 b1 = *(const float4*)(&Bs[cur][kk][tn * 8 + 4]);
            unsigned long long bd[8] = {
                dup2(b0.x), dup2(b0.y), dup2(b0.z), dup2(b0.w),
                dup2(b1.x), dup2(b1.y), dup2(b1.z), dup2(b1.w)};
#pragma unroll
            for (int p = 0; p < 4; p++)
#pragma unroll
                for (int j = 0; j < 8; j++)
                    FFMA2(acc2[p][j], ap[p], bd[j]);
        }

        if (hasNext) G1_STORE(cur ^ 1);
        __syncthreads();
    }

    // ---- K tail: k = 1600 ----
    {
        const int kt = CC - 1;
        unsigned long long at[4];
#pragma unroll
        for (int p = 0; p < 4; p++) {
            int r = row0 + tm * 8 + 2 * p;
            at[p] = pack2(X[(size_t)r * CC + kt], X[(size_t)(r + 1) * CC + kt]);
        }
#pragma unroll
        for (int j = 0; j < 8; j++) {
            int col = tn * 8 + j;
            float bv = (col < 64) ? Ws1[kt * 64 + col] : Wo1[kt * 64 + (col - 64)];
            unsigned long long bd = dup2(bv);
#pragma unroll
            for (int p = 0; p < 4; p++)
                FFMA2(acc2[p][j], at[p], bd);
        }
    }

#pragma unroll
    for (int j = 0; j < 8; j++) {
        int col = tn * 8 + j;
        float bias = (col < 64) ? bs1[col] : bo1[col - 64];
#pragma unroll
        for (int p = 0; p < 4; p++) {
            float lo = __uint_as_float((unsigned)acc2[p][j]);
            float hi = __uint_as_float((unsigned)(acc2[p][j] >> 32));
            g_H[(size_t)(row0 + tm * 8 + 2 * p)     * 128 + col] = fmaxf(lo + bias, 0.f);
            g_H[(size_t)(row0 + tm * 8 + 2 * p + 1) * 128 + col] = fmaxf(hi + bias, 0.f);
        }
    }
}

// ---------------- GEMM2 (R14 verbatim): 64-row x 128-col tiles, FFMA2 ----------------
#define G2_SMEM_FLOATS (128*68 + 128*64)   // 16896
__global__ void __launch_bounds__(256) k_gemm2(
    const float* __restrict__ Ws2, const float* __restrict__ bs2,
    const float* __restrict__ Wo2, const float* __restrict__ bo2)
{
    extern __shared__ float sm2[];
    float (*Ht)[68]  = (float(*)[68])sm2;
    float (*W2s)[64] = (float(*)[64])(sm2 + 128 * 68);

    const int tid = threadIdx.x;
    const int r0 = blockIdx.x * 64;

    for (int i = tid; i < 4096; i += 256) {
        W2s[i >> 6][i & 63] = Ws2[i];
        W2s[64 + (i >> 6)][i & 63] = Wo2[i];
    }
    for (int e4 = tid; e4 < 2048; e4 += 256) {
        int r = e4 >> 5;
        int h4 = e4 & 31;
        float4 v = *(const float4*)(g_H + (size_t)(r0 + r) * 128 + h4 * 4);
        Ht[h4 * 4 + 0][r] = v.x;
        Ht[h4 * 4 + 1][r] = v.y;
        Ht[h4 * 4 + 2][r] = v.z;
        Ht[h4 * 4 + 3][r] = v.w;
    }
    __syncthreads();

    const int tm = tid >> 4;
    const int tn = tid & 15;
    const int hoff = (tn >= 8) ? 64 : 0;
    const int cbase = (tn & 7) * 8;

    unsigned long long acc2[2][8];
#pragma unroll
    for (int p = 0; p < 2; p++)
#pragma unroll
        for (int j = 0; j < 8; j++) acc2[p][j] = 0ull;

#pragma unroll 4
    for (int hh = 0; hh < 64; hh++) {
        const int h = hoff + hh;
        ulonglong2 a01 = *(const ulonglong2*)(&Ht[h][tm * 4]);
        unsigned long long ap[2] = {a01.x, a01.y};
        float4 w0 = *(const float4*)(&W2s[h][cbase]);
        float4 w1 = *(const float4*)(&W2s[h][cbase + 4]);
        unsigned long long bd[8] = {
            dup2(w0.x), dup2(w0.y), dup2(w0.z), dup2(w0.w),
            dup2(w1.x), dup2(w1.y), dup2(w1.z), dup2(w1.w)};
#pragma unroll
        for (int j = 0; j < 8; j++) {
            FFMA2(acc2[0][j], ap[0], bd[j]);
            FFMA2(acc2[1][j], ap[1], bd[j]);
        }
    }

    float b2v[8];
#pragma unroll
    for (int j = 0; j < 8; j++) {
        int col = hoff + cbase + j;
        b2v[j] = (col < 64) ? bs2[col] : bo2[col - 64];
    }
#pragma unroll
    for (int p = 0; p < 2; p++) {
        float lo[8], hi[8];
#pragma unroll
        for (int j = 0; j < 8; j++) {
            lo[j] = __uint_as_float((unsigned)acc2[p][j]) + b2v[j];
            hi[j] = __uint_as_float((unsigned)(acc2[p][j] >> 32)) + b2v[j];
        }
        float* rlo = g_SO + (size_t)(r0 + tm * 4 + 2 * p)     * 128 + hoff + cbase;
        float* rhi = g_SO + (size_t)(r0 + tm * 4 + 2 * p + 1) * 128 + hoff + cbase;
        *(float4*)rlo       = make_float4(lo[0], lo[1], lo[2], lo[3]);
        *(float4*)(rlo + 4) = make_float4(lo[4], lo[5], lo[6], lo[7]);
        *(float4*)rhi       = make_float4(hi[0], hi[1], hi[2], hi[3]);
        *(float4*)(rhi + 4) = make_float4(hi[4], hi[5], hi[6], hi[7]);
    }
}

// ============ Score GEMM (R14 verbatim): scalar staging + u16 keys + 2048-bin histogram ============
#define SCORE_SMEM_FLOATS 18944
__global__ void __launch_bounds__(256, 2) k_score()
{
    extern __shared__ float sm[];
    float (*Ss)[132] = (float(*)[132])sm;
    float (*Os)[132] = (float(*)[132])(sm + 8448);
    unsigned* hist = (unsigned*)(sm + 16896);

    const int tid = threadIdx.x;
    const int b  = blockIdx.z;
    const int i0 = blockIdx.y * 128;
    const int j0 = blockIdx.x * 128;

    for (int h = tid; h < 2048; h += 256) hist[h] = 0;

    for (int e = tid; e < 8192; e += 256) {
        int ii = e >> 6;
        int d  = e & 63;
        int gi = i0 + ii;
        int gj = j0 + ii;
        Ss[d][ii] = (gi < NN) ? g_SO[((size_t)(b * NN + gi)) * 128 + d]      : 0.f;
        Os[d][ii] = (gj < NN) ? g_SO[((size_t)(b * NN + gj)) * 128 + 64 + d] : 0.f;
    }
    __syncthreads();

    const int tm = tid >> 4;
    const int tn = tid & 15;

    unsigned long long acc2[4][8];
#pragma unroll
    for (int p = 0; p < 4; p++)
#pragma unroll
        for (int j = 0; j < 8; j++) acc2[p][j] = 0ull;

#pragma unroll 4
    for (int kk = 0; kk < 64; kk++) {
        ulonglong2 a01 = *(const ulonglong2*)(&Ss[kk][tm * 8]);
        ulonglong2 a23 = *(const ulonglong2*)(&Ss[kk][tm * 8 + 4]);
        unsigned long long ap[4] = {a01.x, a01.y, a23.x, a23.y};
        float4 b0 = *(const float4*)(&Os[kk][tn * 8]);
        float4 b1 = *(const float4*)(&Os[kk][tn * 8 + 4]);
        unsigned long long bd[8] = {
            dup2(b0.x), dup2(b0.y), dup2(b0.z), dup2(b0.w),
            dup2(b1.x), dup2(b1.y), dup2(b1.z), dup2(b1.w)};
#pragma unroll
        for (int p = 0; p < 4; p++)
#pragma unroll
            for (int j = 0; j < 8; j++)
                FFMA2(acc2[p][j], ap[p], bd[j]);
    }

    const int gj0 = j0 + tn * 8;
    if (gj0 < NN) {
#pragma unroll
        for (int p = 0; p < 4; p++) {
#pragma unroll
            for (int half = 0; half < 2; half++) {
                int gi = i0 + tm * 8 + 2 * p + half;
                if (gi >= NN) continue;
                unsigned u[8];
#pragma unroll
                for (int j = 0; j < 8; j++) {
                    unsigned vb = half ? (unsigned)(acc2[p][j] >> 32)
                                       : (unsigned)acc2[p][j];
                    u[j] = flip_bits(vb);
                    atomicAdd(&hist[u[j] >> 21], 1u);
                }
                uint4 packed;
                packed.x = (u[0] >> 16) | (u[1] & 0xFFFF0000u);
                packed.y = (u[2] >> 16) | (u[3] & 0xFFFF0000u);
                packed.z = (u[4] >> 16) | (u[5] & 0xFFFF0000u);
                packed.w = (u[6] >> 16) | (u[7] & 0xFFFF0000u);
                *(uint4*)(g_K + ((size_t)b * NN + gi) * NN + gj0) = packed;
            }
        }
    }
    __syncthreads();
    for (int h = tid; h < 2048; h += 256) {
        unsigned c = hist[h];
        if (c) atomicAdd(&g_cnt1[b * 2048 + h], c);
    }
}

// ---------------- threshold over 2048 bins ----------------
__global__ void __launch_bounds__(256) k_thresh1()
{
    __shared__ unsigned seg[256];
    __shared__ unsigned scan[256];
    const int b = blockIdx.x;
    const int t = threadIdx.x;
    const unsigned* hist = g_cnt1 + b * 2048;

    unsigned s = 0;
#pragma unroll
    for (int q = 0; q < 8; q++) s += hist[2047 - (t * 8 + q)];
    seg[t] = s;
    scan[t] = s;
    __syncthreads();
    for (int off = 1; off < 256; off <<= 1) {
        unsigned v = (t >= off) ? scan[t - off] : 0u;
        __syncthreads();
        scan[t] += v;
        __syncthreads();
    }
    unsigned inc = scan[t];
    unsigned exc = inc - seg[t];
    if (exc < 64u && inc >= 64u) {
        unsigned cum = exc;
        for (int q = 0; q < 8; q++) {
            int bin = 2047 - (t * 8 + q);
            unsigned c = hist[bin];
            if (cum + c >= 64u) { g_b1[b] = bin; g_cntgt1[b] = cum; break; }
            cum += c;
        }
    }
}

// ---- pass 2 (SIMD fast path): emit key16 >= (B1<<5)-1; 32-bin sub-hist of bin1==B1 ----
__global__ void __launch_bounds__(256) k_pass2()
{
    __shared__ unsigned h2[32];
    const int b = blockIdx.y;
    const unsigned B1 = (unsigned)g_b1[b];
    unsigned lo_emit = B1 << 5;
    if (lo_emit) lo_emit--;
    if (threadIdx.x < 32) h2[threadIdx.x] = 0;
    __syncthreads();

    const uint4* K4 = (const uint4*)(g_K + (size_t)b * NN * NN);
    for (int i = blockIdx.x * 256 + threadIdx.x; i < 125000; i += 16 * 256) {
        uint4 q = K4[i];
        unsigned m4 = __vmaxu2(__vmaxu2(q.x, q.y), __vmaxu2(q.z, q.w));
        unsigned mm = m4 >> 16;
        unsigned ml = m4 & 0xFFFFu;
        if ((mm > ml ? mm : ml) < lo_emit) continue;

        unsigned w[4] = {q.x, q.y, q.z, q.w};
#pragma unroll
        for (int l = 0; l < 8; l++) {
            unsigned v = (w[l >> 1] >> ((l & 1) * 16)) & 0xFFFFu;
            if (v >= lo_emit) {
                unsigned idx = atomicAdd(&g_ccnt[b], 1u);
                if (idx < CAP2)
                    g_cand[(size_t)b * CAP2 + idx] =
                        (((unsigned long long)v) << 32) | (unsigned)(i * 8 + l);
            }
            if ((v >> 5) == B1) atomicAdd(&h2[v & 31u], 1u);
        }
    }
    __syncthreads();
    if (threadIdx.x < 32) {
        unsigned c = h2[threadIdx.x];
        if (c) atomicAdd(&g_cnt2[b * 32 + threadIdx.x], c);
    }
}

// ---- final: compute T, filter candidates, recompute exact scores, sort, output ----
__global__ void __launch_bounds__(512) k_sort(float* __restrict__ out)
{
    __shared__ unsigned long long keys[SORTN];
    __shared__ unsigned s_n;
    __shared__ unsigned s_lo;
    const int tid = threadIdx.x;
    const int b = blockIdx.x;

    if (tid == 0) {
        s_n = 0;
        unsigned K = 64u - g_cntgt1[b];
        unsigned cum = 0;
        int bsel = 0;
        for (int bin = 31; bin >= 0; bin--) {
            unsigned c = g_cnt2[b * 32 + bin];
            if (cum + c >= K) { bsel = bin; break; }
            cum += c;
        }
        unsigned T = ((unsigned)g_b1[b] << 5) | (unsigned)bsel;
        s_lo = T ? (T - 1) : 0u;
    }
    __syncthreads();
    const unsigned lo = s_lo;

    unsigned nc = g_ccnt[b];
    if (nc > CAP2) nc = CAP2;

    for (unsigned e = tid; e < nc; e += 512) {
        unsigned long long c = g_cand[(size_t)b * CAP2 + e];
        unsigned v16 = (unsigned)(c >> 32);
        if (v16 >= lo) {
            unsigned idx = atomicAdd(&s_n, 1u);
            if (idx < SORTN) {
                unsigned flat = (unsigned)c;
                int i = flat / NN;
                int j = flat % NN;
                const float4* Sr = (const float4*)(g_SO + ((size_t)(b * NN + i)) * 128);
                const float4* Or = (const float4*)(g_SO + ((size_t)(b * NN + j)) * 128 + 64);
                float acc = 0.f;
#pragma unroll
                for (int k = 0; k < 16; k++) {
                    float4 sv = Sr[k];
                    float4 ov = Or[k];
                    acc = fmaf(sv.x, ov.x, acc);
                    acc = fmaf(sv.y, ov.y, acc);
                    acc = fmaf(sv.z, ov.z, acc);
                    acc = fmaf(sv.w, ov.w, acc);
                }
                keys[idx] = pack_key(sigmoidf_dev(acc), flat);
            }
        }
    }
    __syncthreads();

    int n = (int)s_n;
    if (n > SORTN) n = SORTN;
    int m = 64;
    while (m < n) m <<= 1;
    for (int e = n + tid; e < m; e += 512) keys[e] = 0ull;

    for (int size = 2; size <= m; size <<= 1) {
        for (int stride = size >> 1; stride > 0; stride >>= 1) {
            __syncthreads();
            for (int e = tid; e < m / 2; e += 512) {
                int i = 2 * e - (e & (stride - 1));
                int j = i + stride;
                bool up = ((i & size) == 0);
                unsigned long long a = keys[i], bk = keys[j];
                bool sw = up ? (a < bk) : (a > bk);
                if (sw) { keys[i] = bk; keys[j] = a; }
            }
        }
    }
    __syncthreads();

    if (tid < 64) {
        unsigned long long key = keys[tid];
        unsigned u = (unsigned)(key >> 32);
        unsigned low = (unsigned)key;
        unsigned flat = 0xFFFFFFFFu - low;
        unsigned bits = (u & 0x80000000u) ? (u ^ 0x80000000u) : ~u;
        float s = __uint_as_float(bits);
        int subj = flat / NN;
        int obj = flat % NN;
        out[(b * TAKE_K + tid) * 2 + 0] = (float)subj;
        out[(b * TAKE_K + tid) * 2 + 1] = (float)obj;
        out[BB * TAKE_K * 2 + b * TAKE_K + tid] = s;
    }
}

// ---------------- launch ----------------
extern "C" void kernel_launch(void* const* d_in, const int* in_sizes, int n_in,
                              void* d_out, int out_size)
{
    const float* X   = (const float*)d_in[0];
    const float* Ws1 = (const float*)d_in[2];
    const float* bs1 = (const float*)d_in[3];
    const float* Ws2 = (const float*)d_in[4];
    const float* bs2 = (const float*)d_in[5];
    const float* Wo1 = (const float*)d_in[6];
    const float* bo1 = (const float*)d_in[7];
    const float* Wo2 = (const float*)d_in[8];
    const float* bo2 = (const float*)d_in[9];
    float* out = (float*)d_out;

    static int configured = 0;
    if (!configured) {
        cudaFuncSetAttribute(k_gemm2, cudaFuncAttributeMaxDynamicSharedMemorySize,
                             G2_SMEM_FLOATS * 4);
        cudaFuncSetAttribute(k_score, cudaFuncAttributeMaxDynamicSharedMemorySize,
                             SCORE_SMEM_FLOATS * 4);
        configured = 1;
    }

    k_gemm1<<<MM / 128, 256>>>(X, Ws1, bs1, Wo1, bo1);
    k_gemm2<<<MM / 64, 256, G2_SMEM_FLOATS * 4>>>(Ws2, bs2, Wo2, bo2);
    k_score<<<dim3(8, 8, BB), 256, SCORE_SMEM_FLOATS * 4>>>();
    k_thresh1<<<BB, 256>>>();
    k_pass2<<<dim3(16, BB), 256>>>();
    k_sort<<<BB, 512>>>(out);
}